// round 9
// baseline (speedup 1.0000x reference)
#include <cuda_runtime.h>
#include <cuda_bf16.h>
#include <math_constants.h>

// TemporalAttentionPooling: out[b,d] = softmax_l(mask ? <seq[b,l,:],q>/sqrt(D) : -inf) . seq[b,l,d]
// B=32, L=4096, D=1024. Single-pass online softmax; masked rows skipped
// entirely (~half the HBM traffic).
//
// R9: block-level partial reduction in pass1 (partials 8MB -> 1MB),
// paired-row mainloop (MLP 16, interleaved shfl chains, 1-1.5 FMA/elem),
// query in smem, trivial smem-free pass2.

#define BB 32
#define LL 4096
#define DD 1024
#define PB 8             // partials per batch (one per block)
#define RPB 512          // rows per block (8 warps x 64 rows)

// Scratch (allocation-free rule: __device__ globals).
__device__ float g_part_m [BB * PB];
__device__ float g_part_se[BB * PB];
__device__ float g_part_acc[(size_t)BB * PB * DD];   // 1 MB

// ---------------------------------------------------------------------------
// Pass 1: 256 blocks x 256 threads (8 warps, 2 CTAs/SM).
// Block (b, pblk) owns rows [pblk*512, pblk*512+512) of batch b; warp w owns
// a 64-row slice. Lane k owns columns d = 4k + 128j, j=0..7 (float4, coalesced).
// ---------------------------------------------------------------------------
__global__ void __launch_bounds__(256, 2)
tap_pass1(const float* __restrict__ seq,
          const void* __restrict__ mask_raw,
          const float* __restrict__ query)
{
    __shared__ float s_q[DD];          // 4 KB  query
    __shared__ float s_acc[8][DD];     // 32 KB warp partial accumulators
    __shared__ float s_m[8], s_se[8];

    // ---- inline mask-dtype detection (bool serialized as u8 vs int32) ----
    // Scan first 4 KB (safe under both layouts): int32-bool has every byte at
    // offset %4 != 0 equal to zero; random u8-bool does not (P ~ 2^-3072).
    int any = 0;
    {
        const uint4 v = reinterpret_cast<const uint4*>(mask_raw)[threadIdx.x];
        if ((v.x | v.y | v.z | v.w) & 0xFFFFFF00u) any = 1;
    }
    // Stage query into smem while we're at it.
    reinterpret_cast<float4*>(s_q)[threadIdx.x] =
        reinterpret_cast<const float4*>(query)[threadIdx.x];
    const bool u8 = (__syncthreads_or(any) != 0);

    const int warp = threadIdx.x >> 5;
    const int lane = threadIdx.x & 31;
    const int b    = blockIdx.x >> 3;
    const int pblk = blockIdx.x & 7;
    const int row0 = pblk * RPB + warp * 64;
    const int midx0 = b * LL + row0;

    // ---- 64-bit alive bitmap for this warp's rows (bit r -> row0 + r) ----
    unsigned mA, mB;
    if (u8) {
        const unsigned char* m8 = (const unsigned char*)mask_raw + midx0;
        mA = __ballot_sync(0xffffffffu, m8[lane]      != 0);
        mB = __ballot_sync(0xffffffffu, m8[lane + 32] != 0);
    } else {
        const int* m32 = (const int*)mask_raw + midx0;
        mA = __ballot_sync(0xffffffffu, m32[lane]      != 0);
        mB = __ballot_sync(0xffffffffu, m32[lane + 32] != 0);
    }
    unsigned long long mk = ((unsigned long long)mB << 32) | mA;

    float m  = -CUDART_INF_F;
    float se = 0.0f;
    float4 acc[8];
#pragma unroll
    for (int j = 0; j < 8; j++) acc[j] = make_float4(0.f, 0.f, 0.f, 0.f);

    const float4* srow4 =
        reinterpret_cast<const float4*>(seq + (size_t)b * LL * DD + (size_t)row0 * DD) + lane;
    const float4* q4s = reinterpret_cast<const float4*>(s_q) + lane;

    // ---- mainloop: two alive rows per iteration (order-independent) ----
    while (mk) {
        const int r1 = __ffsll(mk) - 1;
        mk &= mk - 1;

        if (mk) {   // ---- pair path ----
            const int r2 = __ffsll(mk) - 1;
            mk &= mk - 1;

            const float4* x4a = srow4 + (size_t)r1 * (DD / 4);
            const float4* x4b = srow4 + (size_t)r2 * (DD / 4);
            float4 x1[8], x2[8];
#pragma unroll
            for (int j = 0; j < 8; j++) { x1[j] = __ldcs(x4a + 32 * j);
                                          x2[j] = __ldcs(x4b + 32 * j); }

            // Two dots, 4 parallel chains each, interleaved.
            float a0 = 0.f, a1 = 0.f, a2 = 0.f, a3 = 0.f;
            float b0 = 0.f, b1 = 0.f, b2 = 0.f, b3 = 0.f;
#pragma unroll
            for (int j = 0; j < 8; j++) {
                const float4 qv = q4s[32 * j];
                a0 = fmaf(x1[j].x, qv.x, a0);  b0 = fmaf(x2[j].x, qv.x, b0);
                a1 = fmaf(x1[j].y, qv.y, a1);  b1 = fmaf(x2[j].y, qv.y, b1);
                a2 = fmaf(x1[j].z, qv.z, a2);  b2 = fmaf(x2[j].z, qv.z, b2);
                a3 = fmaf(x1[j].w, qv.w, a3);  b3 = fmaf(x2[j].w, qv.w, b3);
            }
            float s1 = (a0 + a1) + (a2 + a3);
            float s2 = (b0 + b1) + (b2 + b3);
#pragma unroll
            for (int o = 16; o > 0; o >>= 1) {   // interleaved chains
                s1 += __shfl_xor_sync(0xffffffffu, s1, o);
                s2 += __shfl_xor_sync(0xffffffffu, s2, o);
            }
            s1 *= 0.03125f;  s2 *= 0.03125f;     // 1/sqrt(1024)

            const float nm = fmaxf(m, fmaxf(s1, s2));
            const float w1 = __expf(s1 - nm);
            const float w2 = __expf(s2 - nm);
            if (nm > m) {                         // warp-uniform branch
                const float rold = __expf(m - nm);   // first pair: exp(-inf)=0
                se = fmaf(se, rold, w1 + w2);
#pragma unroll
                for (int j = 0; j < 8; j++) {
                    acc[j].x = fmaf(acc[j].x, rold, fmaf(w1, x1[j].x, w2 * x2[j].x));
                    acc[j].y = fmaf(acc[j].y, rold, fmaf(w1, x1[j].y, w2 * x2[j].y));
                    acc[j].z = fmaf(acc[j].z, rold, fmaf(w1, x1[j].z, w2 * x2[j].z));
                    acc[j].w = fmaf(acc[j].w, rold, fmaf(w1, x1[j].w, w2 * x2[j].w));
                }
                m = nm;
            } else {
                se += w1 + w2;
#pragma unroll
                for (int j = 0; j < 8; j++) {
                    acc[j].x = fmaf(w1, x1[j].x, fmaf(w2, x2[j].x, acc[j].x));
                    acc[j].y = fmaf(w1, x1[j].y, fmaf(w2, x2[j].y, acc[j].y));
                    acc[j].z = fmaf(w1, x1[j].z, fmaf(w2, x2[j].z, acc[j].z));
                    acc[j].w = fmaf(w1, x1[j].w, fmaf(w2, x2[j].w, acc[j].w));
                }
            }
        } else {    // ---- single leftover row ----
            const float4* x4a = srow4 + (size_t)r1 * (DD / 4);
            float4 x1[8];
#pragma unroll
            for (int j = 0; j < 8; j++) x1[j] = __ldcs(x4a + 32 * j);

            float a0 = 0.f, a1 = 0.f, a2 = 0.f, a3 = 0.f;
#pragma unroll
            for (int j = 0; j < 8; j++) {
                const float4 qv = q4s[32 * j];
                a0 = fmaf(x1[j].x, qv.x, a0);
                a1 = fmaf(x1[j].y, qv.y, a1);
                a2 = fmaf(x1[j].z, qv.z, a2);
                a3 = fmaf(x1[j].w, qv.w, a3);
            }
            float s1 = (a0 + a1) + (a2 + a3);
#pragma unroll
            for (int o = 16; o > 0; o >>= 1)
                s1 += __shfl_xor_sync(0xffffffffu, s1, o);
            s1 *= 0.03125f;

            const float nm = fmaxf(m, s1);
            const float w1 = __expf(s1 - nm);
            const float rold = __expf(m - nm);
            se = fmaf(se, rold, w1);
#pragma unroll
            for (int j = 0; j < 8; j++) {
                acc[j].x = fmaf(acc[j].x, rold, w1 * x1[j].x);
                acc[j].y = fmaf(acc[j].y, rold, w1 * x1[j].y);
                acc[j].z = fmaf(acc[j].z, rold, w1 * x1[j].z);
                acc[j].w = fmaf(acc[j].w, rold, w1 * x1[j].w);
            }
            m = nm;
        }
    }

    // ---- block-level merge of 8 warp partials through smem ----
    float4* sa = reinterpret_cast<float4*>(s_acc[warp]);
#pragma unroll
    for (int j = 0; j < 8; j++) sa[lane + 32 * j] = acc[j];
    if (lane == 0) { s_m[warp] = m; s_se[warp] = se; }
    __syncthreads();

    const int t = threadIdx.x;
    float M = s_m[0];
#pragma unroll
    for (int w = 1; w < 8; w++) M = fmaxf(M, s_m[w]);
    float coef[8];
    float S = 0.f;
#pragma unroll
    for (int w = 0; w < 8; w++) {
        coef[w] = (s_m[w] == -CUDART_INF_F) ? 0.f : __expf(s_m[w] - M);
        S = fmaf(coef[w], s_se[w], S);
    }
#pragma unroll
    for (int k = 0; k < 4; k++) {
        const int col = t + 256 * k;
        float a = 0.f;
#pragma unroll
        for (int w = 0; w < 8; w++) a = fmaf(coef[w], s_acc[w][col], a);
        g_part_acc[(size_t)blockIdx.x * DD + col] = a;
    }
    if (t == 0) { g_part_m[blockIdx.x] = M; g_part_se[blockIdx.x] = S; }
}

// ---------------------------------------------------------------------------
// Pass 2: grid (B, 4) x 256 threads. Block (b,q) handles cols [q*256, q*256+256).
// Only 8 partials per batch now -> all-thread redundant LSE, no smem, 1 MB read.
// ---------------------------------------------------------------------------
__global__ void __launch_bounds__(256)
tap_pass2(float* __restrict__ out)
{
    const int b = blockIdx.x;
    const int d = blockIdx.y * 256 + threadIdx.x;

    float pm[8], ps[8];
#pragma unroll
    for (int w = 0; w < 8; w++) { pm[w] = g_part_m [b * PB + w];
                                  ps[w] = g_part_se[b * PB + w]; }
    float M = pm[0];
#pragma unroll
    for (int w = 1; w < 8; w++) M = fmaxf(M, pm[w]);
    float coef[8];
    float S = 0.f;
#pragma unroll
    for (int w = 0; w < 8; w++) {
        coef[w] = (pm[w] == -CUDART_INF_F) ? 0.f : __expf(pm[w] - M);
        S = fmaf(coef[w], ps[w], S);
    }
    const float inv = 1.0f / S;

    const float* base = g_part_acc + (size_t)b * PB * DD + d;
    float a = 0.f;
#pragma unroll
    for (int w = 0; w < 8; w++) a = fmaf(coef[w], base[(size_t)w * DD], a);
    out[(size_t)b * DD + d] = a * inv;
}

// ---------------------------------------------------------------------------
extern "C" void kernel_launch(void* const* d_in, const int* in_sizes, int n_in,
                              void* d_out, int out_size)
{
    // Bind inputs by element count (ordering-proof):
    //   sequence: 134217728, mask: 131072, query: 1024
    const float* seq   = nullptr;
    const void*  mask  = nullptr;
    const float* query = nullptr;
    for (int i = 0; i < n_in; i++) {
        if      (in_sizes[i] == BB * LL * DD) seq   = (const float*)d_in[i];
        else if (in_sizes[i] == BB * LL)      mask  = d_in[i];
        else if (in_sizes[i] == DD)           query = (const float*)d_in[i];
    }
    float* out = (float*)d_out;
    (void)out_size;

    tap_pass1<<<BB * PB, 256>>>(seq, mask, query);
    tap_pass2<<<dim3(BB, 4), 256>>>(out);
}

// round 10
// speedup vs baseline: 1.0790x; 1.0790x over previous
#include <cuda_runtime.h>
#include <cuda_bf16.h>
#include <math_constants.h>

// TemporalAttentionPooling: out[b,d] = softmax_l(mask ? <seq[b,l,:],q>/sqrt(D) : -inf) . seq[b,l,d]
// B=32, L=4096, D=1024. Single kernel: online softmax with masked-row skip
// (~half the HBM traffic), block-level smem merge (8 partials/batch, 1 MB),
// fused last-block-per-batch finalization (threadfence reduction) -> no pass2.
//
// R10: mainloop reverted to R8 (register query, single row/iter, deferred
// rescale) — R9's paired-row + smem-query variant spilled and regressed.

#define BB 32
#define LL 4096
#define DD 1024
#define PB 8             // partial blocks per batch
#define RPB 512          // rows per block (8 warps x 64 rows)

// Scratch (allocation-free rule: __device__ globals; zero-initialized).
__device__ float g_part_m [BB * PB];
__device__ float g_part_se[BB * PB];
__device__ float g_part_acc[(size_t)BB * PB * DD];   // 1 MB
__device__ int   g_cnt[BB];                          // per-batch arrival counters

// ---------------------------------------------------------------------------
// 256 blocks x 256 threads (8 warps, 2 CTAs/SM).
// Block (b, pblk) owns rows [pblk*512, +512) of batch b; warp w owns 64 rows.
// Lane k owns columns d = 4k + 128j, j=0..7 -> float4, fully coalesced.
// ---------------------------------------------------------------------------
__global__ void __launch_bounds__(256, 2)
tap_fused(const float* __restrict__ seq,
          const void* __restrict__ mask_raw,
          const float* __restrict__ query,
          float* __restrict__ out)
{
    __shared__ float s_acc[8][DD];     // 32 KB warp partial accumulators
    __shared__ float s_m[8], s_se[8];
    __shared__ int   s_last;

    // ---- inline mask-dtype detection (bool serialized as u8 vs int32) ----
    // Scan first 4 KB (safe under both layouts): int32-bool has every byte at
    // offset %4 != 0 equal to zero; random u8-bool does not (P ~ 2^-3072).
    int any = 0;
    {
        const uint4 v = reinterpret_cast<const uint4*>(mask_raw)[threadIdx.x];
        if ((v.x | v.y | v.z | v.w) & 0xFFFFFF00u) any = 1;
    }
    const bool u8 = (__syncthreads_or(any) != 0);

    const int warp = threadIdx.x >> 5;
    const int lane = threadIdx.x & 31;
    const int b    = blockIdx.x >> 3;
    const int pblk = blockIdx.x & 7;
    const int row0 = pblk * RPB + warp * 64;
    const int midx0 = b * LL + row0;

    // ---- 64-bit alive bitmap for this warp's rows (bit r -> row0 + r) ----
    unsigned mA, mB;
    if (u8) {
        const unsigned char* m8 = (const unsigned char*)mask_raw + midx0;
        mA = __ballot_sync(0xffffffffu, m8[lane]      != 0);
        mB = __ballot_sync(0xffffffffu, m8[lane + 32] != 0);
    } else {
        const int* m32 = (const int*)mask_raw + midx0;
        mA = __ballot_sync(0xffffffffu, m32[lane]      != 0);
        mB = __ballot_sync(0xffffffffu, m32[lane + 32] != 0);
    }
    unsigned long long mk = ((unsigned long long)mB << 32) | mA;

    // Query fragment in registers (R8-style; no LDS in the hot loop).
    float4 qf[8];
    const float4* q4 = reinterpret_cast<const float4*>(query);
#pragma unroll
    for (int j = 0; j < 8; j++) qf[j] = q4[lane + 32 * j];

    float m  = -CUDART_INF_F;
    float se = 0.0f;
    float4 acc[8];
#pragma unroll
    for (int j = 0; j < 8; j++) acc[j] = make_float4(0.f, 0.f, 0.f, 0.f);

    const float4* srow4 =
        reinterpret_cast<const float4*>(seq + (size_t)b * LL * DD + (size_t)row0 * DD) + lane;

    // ---- mainloop: one alive row per iteration (order-independent) ----
    while (mk) {
        const int r = __ffsll(mk) - 1;
        mk &= mk - 1;

        // 8 streaming float4 loads (512B warp wavefronts, MLP=8).
        const float4* x4 = srow4 + (size_t)r * (DD / 4);
        float4 x[8];
#pragma unroll
        for (int j = 0; j < 8; j++) x[j] = __ldcs(x4 + 32 * j);

        // Dot with query: 4 parallel FMA chains.
        float s0 = 0.f, s1 = 0.f, s2 = 0.f, s3 = 0.f;
#pragma unroll
        for (int j = 0; j < 8; j++) {
            s0 = fmaf(x[j].x, qf[j].x, s0);
            s1 = fmaf(x[j].y, qf[j].y, s1);
            s2 = fmaf(x[j].z, qf[j].z, s2);
            s3 = fmaf(x[j].w, qf[j].w, s3);
        }
        float s = (s0 + s1) + (s2 + s3);
#pragma unroll
        for (int o = 16; o > 0; o >>= 1)
            s += __shfl_xor_sync(0xffffffffu, s, o);
        s *= 0.03125f;   // 1/sqrt(1024)

        // Deferred-rescale online softmax (branch is warp-uniform).
        if (s > m) {
            const float rold = __expf(m - s);   // first row: exp(-inf)=0
            se = fmaf(se, rold, 1.0f);
#pragma unroll
            for (int j = 0; j < 8; j++) {       // w = 1
                acc[j].x = fmaf(acc[j].x, rold, x[j].x);
                acc[j].y = fmaf(acc[j].y, rold, x[j].y);
                acc[j].z = fmaf(acc[j].z, rold, x[j].z);
                acc[j].w = fmaf(acc[j].w, rold, x[j].w);
            }
            m = s;
        } else {
            const float w = __expf(s - m);
            se += w;
#pragma unroll
            for (int j = 0; j < 8; j++) {
                acc[j].x = fmaf(w, x[j].x, acc[j].x);
                acc[j].y = fmaf(w, x[j].y, acc[j].y);
                acc[j].z = fmaf(w, x[j].z, acc[j].z);
                acc[j].w = fmaf(w, x[j].w, acc[j].w);
            }
        }
    }

    // ---- block-level merge of 8 warp partials through smem ----
    float4* sa = reinterpret_cast<float4*>(s_acc[warp]);
#pragma unroll
    for (int j = 0; j < 8; j++) sa[lane + 32 * j] = acc[j];
    if (lane == 0) { s_m[warp] = m; s_se[warp] = se; }
    __syncthreads();

    const int t = threadIdx.x;
    {
        float M = s_m[0];
#pragma unroll
        for (int w = 1; w < 8; w++) M = fmaxf(M, s_m[w]);
        float coef[8];
        float S = 0.f;
#pragma unroll
        for (int w = 0; w < 8; w++) {
            coef[w] = (s_m[w] == -CUDART_INF_F) ? 0.f : __expf(s_m[w] - M);
            S = fmaf(coef[w], s_se[w], S);
        }
#pragma unroll
        for (int k = 0; k < 4; k++) {
            const int col = t + 256 * k;
            float a = 0.f;
#pragma unroll
            for (int w = 0; w < 8; w++) a = fmaf(coef[w], s_acc[w][col], a);
            g_part_acc[(size_t)blockIdx.x * DD + col] = a;
        }
        if (t == 0) { g_part_m[blockIdx.x] = M; g_part_se[blockIdx.x] = S; }
    }

    // ---- fused finalization: last block of this batch merges 8 partials ----
    if (t == 0) {
        __threadfence();                       // publish partial before arrival
        const int old = atomicAdd(&g_cnt[b], 1);
        s_last = (old == PB - 1);
    }
    __syncthreads();
    if (!s_last) return;
    __threadfence();                           // acquire other blocks' partials

    float pm[8], ps[8];
#pragma unroll
    for (int w = 0; w < 8; w++) {
        pm[w] = __ldcg(&g_part_m [b * PB + w]);
        ps[w] = __ldcg(&g_part_se[b * PB + w]);
    }
    float M = pm[0];
#pragma unroll
    for (int w = 1; w < 8; w++) M = fmaxf(M, pm[w]);
    float coef[8];
    float S = 0.f;
#pragma unroll
    for (int w = 0; w < 8; w++) {
        coef[w] = (pm[w] == -CUDART_INF_F) ? 0.f : __expf(pm[w] - M);
        S = fmaf(coef[w], ps[w], S);
    }
    const float inv = 1.0f / S;

    const float* base = g_part_acc + (size_t)b * PB * DD;
#pragma unroll
    for (int k = 0; k < 4; k++) {
        const int col = t + 256 * k;
        float a = 0.f;
#pragma unroll
        for (int w = 0; w < 8; w++)
            a = fmaf(coef[w], __ldcg(base + (size_t)w * DD + col), a);
        out[(size_t)b * DD + col] = a * inv;
    }
    if (t == 0) g_cnt[b] = 0;                  // reset for next graph replay
}

// ---------------------------------------------------------------------------
extern "C" void kernel_launch(void* const* d_in, const int* in_sizes, int n_in,
                              void* d_out, int out_size)
{
    // Bind inputs by element count (ordering-proof):
    //   sequence: 134217728, mask: 131072, query: 1024
    const float* seq   = nullptr;
    const void*  mask  = nullptr;
    const float* query = nullptr;
    for (int i = 0; i < n_in; i++) {
        if      (in_sizes[i] == BB * LL * DD) seq   = (const float*)d_in[i];
        else if (in_sizes[i] == BB * LL)      mask  = d_in[i];
        else if (in_sizes[i] == DD)           query = (const float*)d_in[i];
    }
    float* out = (float*)d_out;
    (void)out_size;

    tap_fused<<<BB * PB, 256>>>(seq, mask, query, out);
}